// round 13
// baseline (speedup 1.0000x reference)
#include <cuda_runtime.h>
#include <cuda_fp16.h>
#include <math.h>
#include <stdint.h>

#define BATCH 2
#define SEQ   2048
#define DIM   1024
#define NH    16
#define DHD   64
#define MROWS (BATCH*SEQ)   // 4096

// ---------------- scratch (device globals: allocation-free) ----------------
__device__ __half g_Xh[(size_t)MROWS * DIM], g_Xl[(size_t)MROWS * DIM];
__device__ __half g_Wqh[(size_t)DIM * DIM];
__device__ __half g_Wkh[(size_t)DIM * DIM];
__device__ __half g_Wvh[(size_t)DIM * DIM];
__device__ __half g_Woh[(size_t)DIM * DIM];
__device__ __half g_Qh[(size_t)MROWS * DIM], g_Ql[(size_t)MROWS * DIM];
__device__ __half g_Kh[(size_t)MROWS * DIM], g_Kl[(size_t)MROWS * DIM];
__device__ __half g_Vh[(size_t)MROWS * DIM], g_Vl[(size_t)MROWS * DIM];
__device__ __half g_Ch[(size_t)MROWS * DIM], g_Cl[(size_t)MROWS * DIM];

// ---------------- helpers ---------------------------------------------------
__device__ __forceinline__ uint32_t smem_u32(const void* p) {
    return (uint32_t)__cvta_generic_to_shared(p);
}
__device__ __forceinline__ void cp16(uint32_t dst, const void* src) {
    asm volatile("cp.async.cg.shared.global [%0], [%1], 16;"
                 :: "r"(dst), "l"(src));
}
__device__ __forceinline__ void cp16p(void* dst, const void* src) {
    asm volatile("cp.async.cg.shared.global [%0], [%1], 16;"
                 :: "r"(smem_u32(dst)), "l"(src));
}
#define CP_COMMIT() asm volatile("cp.async.commit_group;")
#define CP_WAIT(n)  asm volatile("cp.async.wait_group %0;" :: "n"(n))

__device__ __forceinline__ void ldm_x4(uint32_t* r, uint32_t addr) {
    asm volatile("ldmatrix.sync.aligned.m8n8.x4.shared.b16 {%0,%1,%2,%3}, [%4];"
                 : "=r"(r[0]), "=r"(r[1]), "=r"(r[2]), "=r"(r[3]) : "r"(addr));
}
__device__ __forceinline__ void ldm_x4t(uint32_t* r, uint32_t addr) {
    asm volatile("ldmatrix.sync.aligned.m8n8.x4.trans.shared.b16 {%0,%1,%2,%3}, [%4];"
                 : "=r"(r[0]), "=r"(r[1]), "=r"(r[2]), "=r"(r[3]) : "r"(addr));
}
__device__ __forceinline__ void mma16(float* d, const uint32_t* a, const uint32_t* b) {
    asm volatile("mma.sync.aligned.m16n8k16.row.col.f32.f16.f16.f32 "
                 "{%0,%1,%2,%3}, {%4,%5,%6,%7}, {%8,%9}, {%0,%1,%2,%3};"
                 : "+f"(d[0]), "+f"(d[1]), "+f"(d[2]), "+f"(d[3])
                 : "r"(a[0]), "r"(a[1]), "r"(a[2]), "r"(a[3]),
                   "r"(b[0]), "r"(b[1]));
}
__device__ __forceinline__ void split2(float x, __half& h, __half& l) {
    h = __float2half_rn(x);
    l = __float2half_rn(x - __half2float(h));
}

// ---------------- split kernels ---------------------------------------------
__global__ __launch_bounds__(256) void split_kernel(
    const float4* __restrict__ src, __half2* __restrict__ hi,
    __half2* __restrict__ lo, int n4)
{
    int i = blockIdx.x * 256 + threadIdx.x;
    if (i >= n4) return;
    float4 v = src[i];
    __half h0, l0, h1, l1;
    split2(v.x, h0, l0); split2(v.y, h1, l1);
    hi[2 * i]     = __halves2half2(h0, h1);
    lo[2 * i]     = __halves2half2(l0, l1);
    split2(v.z, h0, l0); split2(v.w, h1, l1);
    hi[2 * i + 1] = __halves2half2(h0, h1);
    lo[2 * i + 1] = __halves2half2(l0, l1);
}

// hi-only split for 4 weight matrices fused in one launch (blockIdx.y picks)
__global__ __launch_bounds__(256) void splitw_kernel(
    const float4* __restrict__ s0, const float4* __restrict__ s1,
    const float4* __restrict__ s2, const float4* __restrict__ s3,
    __half2* __restrict__ d0, __half2* __restrict__ d1,
    __half2* __restrict__ d2, __half2* __restrict__ d3, int n4)
{
    int w = blockIdx.y;
    const float4* s = (w == 0) ? s0 : (w == 1) ? s1 : (w == 2) ? s2 : s3;
    __half2* d      = (w == 0) ? d0 : (w == 1) ? d1 : (w == 2) ? d2 : d3;
    int i = blockIdx.x * 256 + threadIdx.x;
    if (i >= n4) return;
    float4 v = s[i];
    d[2 * i]     = __halves2half2(__float2half_rn(v.x), __float2half_rn(v.y));
    d[2 * i + 1] = __halves2half2(__float2half_rn(v.z), __float2half_rn(v.w));
}

// ============================================================================
// GEMM core (unchanged): CTA 64x128, BK=32, warp 32x32, 2-term (Ah+Al)·Bh.
// ============================================================================
#define APITCH 40
#define BPITCH 136
#define A_BYTES (64 * APITCH * 2)
#define B_BYTES (32 * BPITCH * 2)
#define OFF_AH 0
#define OFF_AL A_BYTES
#define OFF_BH (2 * A_BYTES)
#define BUF_BYTES (2 * A_BYTES + B_BYTES)   // 18944
#define GEMM_SMEM (2 * BUF_BYTES)           // 37888

struct GemmOut {
    float*  Cf;
    __half* Ch;
    __half* Cl;
};

template<bool SPLIT_OUT>
__device__ __forceinline__ void gemm_body(
    const __half* __restrict__ Ah_g, const __half* __restrict__ Al_g,
    const __half* __restrict__ Bh_g,
    const float* __restrict__ bias, float out_scale, GemmOut o,
    int rowBase, int colBase, uint32_t sb)
{
    const int tid  = threadIdx.x;
    const int wid  = tid >> 5, lane = tid & 31;
    const int wrow = wid >> 2;
    const int wcol = wid & 3;
    const int rr = lane & 7, g = lane >> 3;

    float acc[2][4][4];
#pragma unroll
    for (int mt = 0; mt < 2; mt++)
#pragma unroll
        for (int nt = 0; nt < 4; nt++)
#pragma unroll
            for (int e = 0; e < 4; e++) acc[mt][nt][e] = 0.f;

    auto loadTile = [&](int buf, int k0) {
        uint32_t b = sb + buf * BUF_BYTES;
        {
            int r = tid >> 2, c16 = (tid & 3) << 4;
            size_t go = (size_t)(rowBase + r) * DIM + k0 + (c16 >> 1);
            uint32_t so = (uint32_t)(r * (APITCH * 2) + c16);
            cp16(b + OFF_AH + so, Ah_g + go);
            cp16(b + OFF_AL + so, Al_g + go);
        }
#pragma unroll
        for (int i = 0; i < 2; i++) {
            int idx = tid + i * 256;
            int r = idx >> 4, c16 = (idx & 15) << 4;
            size_t go = (size_t)(k0 + r) * DIM + colBase + (c16 >> 1);
            uint32_t so = (uint32_t)(r * (BPITCH * 2) + c16);
            cp16(b + OFF_BH + so, Bh_g + go);
        }
    };

    loadTile(0, 0); CP_COMMIT();

    const int T = DIM / 32;
#pragma unroll 1
    for (int t = 0; t < T; t++) {
        if (t + 1 < T) { loadTile((t + 1) & 1, (t + 1) * 32); CP_COMMIT(); CP_WAIT(1); }
        else           { CP_WAIT(0); }
        __syncthreads();

        const uint32_t bb = sb + (t & 1) * BUF_BYTES;

#pragma unroll
        for (int ks = 0; ks < 2; ks++) {
            const int kl = ks * 16;
            uint32_t ahf[2][4], alf[2][4];
#pragma unroll
            for (int mt = 0; mt < 2; mt++) {
                int row = wrow * 32 + mt * 16 + rr + ((g & 1) << 3);
                int col = kl + ((g >> 1) << 3);
                uint32_t off = (uint32_t)(row * (APITCH * 2) + col * 2);
                ldm_x4(ahf[mt], bb + OFF_AH + off);
                ldm_x4(alf[mt], bb + OFF_AL + off);
            }
#pragma unroll
            for (int ntp = 0; ntp < 2; ntp++) {
                int brow = kl + rr + (((lane >> 3) & 1) << 3);
                int bcol = wcol * 32 + ntp * 16 + ((lane >> 4) << 3);
                uint32_t off = (uint32_t)(brow * (BPITCH * 2) + bcol * 2);
                uint32_t bh[4];
                ldm_x4t(bh, bb + OFF_BH + off);
#pragma unroll
                for (int mt = 0; mt < 2; mt++) {
                    mma16(acc[mt][2 * ntp],     ahf[mt], bh);
                    mma16(acc[mt][2 * ntp],     alf[mt], bh);
                    mma16(acc[mt][2 * ntp + 1], ahf[mt], bh + 2);
                    mma16(acc[mt][2 * ntp + 1], alf[mt], bh + 2);
                }
            }
        }
        __syncthreads();
    }

#pragma unroll
    for (int mt = 0; mt < 2; mt++) {
        int r0 = rowBase + wrow * 32 + mt * 16 + (lane >> 2);
#pragma unroll
        for (int nt = 0; nt < 4; nt++) {
            int c0 = colBase + wcol * 32 + nt * 8 + ((lane & 3) << 1);
            float b0 = bias[c0], b1 = bias[c0 + 1];
            float v00 = (acc[mt][nt][0] + b0) * out_scale;
            float v01 = (acc[mt][nt][1] + b1) * out_scale;
            float v10 = (acc[mt][nt][2] + b0) * out_scale;
            float v11 = (acc[mt][nt][3] + b1) * out_scale;
            if (SPLIT_OUT) {
                __half h0, l0, h1, l1;
                split2(v00, h0, l0); split2(v01, h1, l1);
                *(__half2*)&o.Ch[(size_t)r0 * DIM + c0] = __halves2half2(h0, h1);
                *(__half2*)&o.Cl[(size_t)r0 * DIM + c0] = __halves2half2(l0, l1);
                split2(v10, h0, l0); split2(v11, h1, l1);
                *(__half2*)&o.Ch[(size_t)(r0 + 8) * DIM + c0] = __halves2half2(h0, h1);
                *(__half2*)&o.Cl[(size_t)(r0 + 8) * DIM + c0] = __halves2half2(l0, l1);
            } else {
                o.Cf[(size_t)r0 * DIM + c0]           = v00;
                o.Cf[(size_t)r0 * DIM + c0 + 1]       = v01;
                o.Cf[(size_t)(r0 + 8) * DIM + c0]     = v10;
                o.Cf[(size_t)(r0 + 8) * DIM + c0 + 1] = v11;
            }
        }
    }
}

__global__ __launch_bounds__(256) void gemmqkv_kernel(
    const __half* __restrict__ Xh, const __half* __restrict__ Xl,
    const __half* __restrict__ Wqh, const __half* __restrict__ Wkh,
    const __half* __restrict__ Wvh,
    const float* __restrict__ bq, const float* __restrict__ bk,
    const float* __restrict__ bv,
    __half* __restrict__ Qh, __half* __restrict__ Ql,
    __half* __restrict__ Kh, __half* __restrict__ Kl,
    __half* __restrict__ Vh, __half* __restrict__ Vl)
{
    extern __shared__ __align__(16) char dsm[];
    const int z = blockIdx.z;
    const __half* Bh = (z == 0) ? Wqh : (z == 1) ? Wkh : Wvh;
    const float*  bs = (z == 0) ? bq  : (z == 1) ? bk  : bv;
    GemmOut o;
    o.Cf = nullptr;
    o.Ch = (z == 0) ? Qh : (z == 1) ? Kh : Vh;
    o.Cl = (z == 0) ? Ql : (z == 1) ? Kl : Vl;
    float sc = (z == 0) ? 0.125f : 1.0f;
    gemm_body<true>(Xh, Xl, Bh, bs, sc, o,
                    blockIdx.y * 64, blockIdx.x * 128, smem_u32(dsm));
}

__global__ __launch_bounds__(256) void gemmo_kernel(
    const __half* __restrict__ Ah, const __half* __restrict__ Al,
    const __half* __restrict__ Bh,
    const float* __restrict__ bias, float* __restrict__ out)
{
    extern __shared__ __align__(16) char dsm[];
    GemmOut o; o.Cf = out; o.Ch = nullptr; o.Cl = nullptr;
    gemm_body<false>(Ah, Al, Bh, bias, 1.0f, o,
                     blockIdx.y * 64, blockIdx.x * 128, smem_u32(dsm));
}

// ============================================================================
// Flash attention — single-term MMAs: S = Qh·Kh, ctx += Ph·Vh.
// (error absorbed by fp32 accumulation + 1e-3 gate; hi/lo kept only in
// the projection GEMMs and the ctx output feeding the O-projection)
// K/V hi-only smem, 2 CTAs/SM, 256 threads, 128 q-rows, double-buffered.
// ============================================================================
#define FPAD 72
#define KVOFF_V 2304   // 32*FPAD halfs

__global__ __launch_bounds__(256, 2) void flash16_kernel(
    const __half* __restrict__ Qh_g,
    const __half* __restrict__ Kh_g, const __half* __restrict__ Vh_g,
    const float* __restrict__ mask,
    __half* __restrict__ Ch_g, __half* __restrict__ Cl_g)
{
    __shared__ __align__(16) __half fsm[2][128 * FPAD];   // Q staging, then K/V x2
    __shared__ __align__(16) float maskS[2][32];

    const int b = blockIdx.z, h = blockIdx.y;
    const int q0 = blockIdx.x * 128;
    const int tid = threadIdx.x, wid = tid >> 5, lane = tid & 31;
    const int rr = lane & 7, g = lane >> 3;
    const size_t base = ((size_t)b * SEQ) * DIM + (size_t)h * DHD;

    // ---- stage Q (hi only), preload fragments ----
#pragma unroll
    for (int i = 0; i < 4; i++) {
        int idx = tid + i * 256;
        int r = idx >> 3, c8 = (idx & 7) << 3;
        if (r < 128) {
            size_t go = base + (size_t)(q0 + r) * DIM + c8;
            cp16p(&fsm[0][r * FPAD + c8], Qh_g + go);
        }
    }
    CP_COMMIT(); CP_WAIT(0);
    __syncthreads();

    const int m0 = wid * 16;
    const int qrow = m0 + rr + ((g & 1) << 3);
    const int qcoff = (g >> 1) << 3;
    uint32_t qfh[4][4];
#pragma unroll
    for (int ks = 0; ks < 4; ks++)
        ldm_x4(qfh[ks], smem_u32(&fsm[0][qrow * FPAD + ks * 16 + qcoff]));
    __syncthreads();   // Q smem reusable as K/V double buffer

    auto loadKV = [&](int buf, int kt) {
        __half* s = fsm[buf];
        int r = tid >> 3, c8 = (tid & 7) << 3;
        size_t go = base + (size_t)(kt + r) * DIM + c8;
        cp16p(&s[          r * FPAD + c8], Kh_g + go);
        cp16p(&s[KVOFF_V + r * FPAD + c8], Vh_g + go);
        if (tid < 8) cp16p(&maskS[buf][tid * 4], mask + (size_t)b * SEQ + kt + tid * 4);
    };

    float m0r = -1e30f, m1r = -1e30f, l0r = 0.f, l1r = 0.f;
    float ctx[8][4];
#pragma unroll
    for (int nt = 0; nt < 8; nt++)
#pragma unroll
        for (int e = 0; e < 4; e++) ctx[nt][e] = 0.f;

    loadKV(0, 0); CP_COMMIT();

#pragma unroll 1
    for (int t = 0; t < SEQ / 32; t++) {
        if (t < SEQ / 32 - 1) { loadKV((t + 1) & 1, (t + 1) * 32); CP_COMMIT(); }
        if (t < SEQ / 32 - 1) { CP_WAIT(1); } else { CP_WAIT(0); }
        __syncthreads();

        const __half* Ks = fsm[t & 1];
        const float*  mS = maskS[t & 1];

        // ---- scores S[16x32]: Qh · Kh ----
        float s[4][4];
#pragma unroll
        for (int nt = 0; nt < 4; nt++)
#pragma unroll
            for (int e = 0; e < 4; e++) s[nt][e] = 0.f;

#pragma unroll
        for (int ks = 0; ks < 4; ks++) {
#pragma unroll
            for (int ntp = 0; ntp < 2; ntp++) {
                int krow = ntp * 16 + ((lane >> 4) << 3) + rr;
                int kcol = ks * 16 + (((lane >> 3) & 1) << 3);
                uint32_t kh[4];
                ldm_x4(kh, smem_u32(&Ks[krow * FPAD + kcol]));
                mma16(s[2 * ntp],     qfh[ks], kh);
                mma16(s[2 * ntp + 1], qfh[ks], kh + 2);
            }
        }

        // ---- mask ----
#pragma unroll
        for (int nt = 0; nt < 4; nt++) {
            int c = nt * 8 + ((lane & 3) << 1);
            float mv0 = fmaf(mS[c],     1e6f, -1e6f);
            float mv1 = fmaf(mS[c + 1], 1e6f, -1e6f);
            s[nt][0] += mv0; s[nt][1] += mv1;
            s[nt][2] += mv0; s[nt][3] += mv1;
        }

        // ---- online softmax ----
        float rmax0 = -1e30f, rmax1 = -1e30f;
#pragma unroll
        for (int nt = 0; nt < 4; nt++) {
            rmax0 = fmaxf(rmax0, fmaxf(s[nt][0], s[nt][1]));
            rmax1 = fmaxf(rmax1, fmaxf(s[nt][2], s[nt][3]));
        }
        rmax0 = fmaxf(rmax0, __shfl_xor_sync(0xffffffffu, rmax0, 1));
        rmax0 = fmaxf(rmax0, __shfl_xor_sync(0xffffffffu, rmax0, 2));
        rmax1 = fmaxf(rmax1, __shfl_xor_sync(0xffffffffu, rmax1, 1));
        rmax1 = fmaxf(rmax1, __shfl_xor_sync(0xffffffffu, rmax1, 2));
        float newm0 = fmaxf(m0r, rmax0), newm1 = fmaxf(m1r, rmax1);
        float fac0 = __expf(m0r - newm0), fac1 = __expf(m1r - newm1);
        m0r = newm0; m1r = newm1;

        float p[4][4];
        float rsum0 = 0.f, rsum1 = 0.f;
#pragma unroll
        for (int nt = 0; nt < 4; nt++) {
            p[nt][0] = __expf(s[nt][0] - newm0);
            p[nt][1] = __expf(s[nt][1] - newm0);
            p[nt][2] = __expf(s[nt][2] - newm1);
            p[nt][3] = __expf(s[nt][3] - newm1);
            rsum0 += p[nt][0] + p[nt][1];
            rsum1 += p[nt][2] + p[nt][3];
        }
        rsum0 += __shfl_xor_sync(0xffffffffu, rsum0, 1);
        rsum0 += __shfl_xor_sync(0xffffffffu, rsum0, 2);
        rsum1 += __shfl_xor_sync(0xffffffffu, rsum1, 1);
        rsum1 += __shfl_xor_sync(0xffffffffu, rsum1, 2);
        l0r = l0r * fac0 + rsum0;
        l1r = l1r * fac1 + rsum1;

#pragma unroll
        for (int nt = 0; nt < 8; nt++) {
            ctx[nt][0] *= fac0; ctx[nt][1] *= fac0;
            ctx[nt][2] *= fac1; ctx[nt][3] *= fac1;
        }

        // ---- pack P hi A-fragments (single term) ----
        uint32_t pah[2][4];
#pragma unroll
        for (int kb = 0; kb < 2; kb++) {
            int t0 = kb * 2, t1 = kb * 2 + 1;
            __half h0, h1;
            h0 = __float2half_rn(p[t0][0]); h1 = __float2half_rn(p[t0][1]);
            pah[kb][0] = (uint32_t)__half_as_ushort(h0) | ((uint32_t)__half_as_ushort(h1) << 16);
            h0 = __float2half_rn(p[t0][2]); h1 = __float2half_rn(p[t0][3]);
            pah[kb][1] = (uint32_t)__half_as_ushort(h0) | ((uint32_t)__half_as_ushort(h1) << 16);
            h0 = __float2half_rn(p[t1][0]); h1 = __float2half_rn(p[t1][1]);
            pah[kb][2] = (uint32_t)__half_as_ushort(h0) | ((uint32_t)__half_as_ushort(h1) << 16);
            h0 = __float2half_rn(p[t1][2]); h1 = __float2half_rn(p[t1][3]);
            pah[kb][3] = (uint32_t)__half_as_ushort(h0) | ((uint32_t)__half_as_ushort(h1) << 16);
        }

        // ---- ctx += Ph · Vh ----
#pragma unroll
        for (int kb = 0; kb < 2; kb++) {
            int vrow = kb * 16 + rr + (((lane >> 3) & 1) << 3);
#pragma unroll
            for (int ntp = 0; ntp < 4; ntp++) {
                int vcol = ntp * 16 + ((lane >> 4) << 3);
                uint32_t vh[4];
                ldm_x4t(vh, smem_u32(&Ks[KVOFF_V + vrow * FPAD + vcol]));
                mma16(ctx[2 * ntp],     pah[kb], vh);
                mma16(ctx[2 * ntp + 1], pah[kb], vh + 2);
            }
        }
        __syncthreads();
    }

    float inv0 = 1.f / l0r, inv1 = 1.f / l1r;
    int r0 = q0 + m0 + (lane >> 2);
#pragma unroll
    for (int nt = 0; nt < 8; nt++) {
        int c0 = nt * 8 + ((lane & 3) << 1);
        __half h0, l0, h1, l1;
        split2(ctx[nt][0] * inv0, h0, l0); split2(ctx[nt][1] * inv0, h1, l1);
        *(__half2*)&Ch_g[base + (size_t)r0 * DIM + c0] = __halves2half2(h0, h1);
        *(__half2*)&Cl_g[base + (size_t)r0 * DIM + c0] = __halves2half2(l0, l1);
        split2(ctx[nt][2] * inv1, h0, l0); split2(ctx[nt][3] * inv1, h1, l1);
        *(__half2*)&Ch_g[base + (size_t)(r0 + 8) * DIM + c0] = __halves2half2(h0, h1);
        *(__half2*)&Cl_g[base + (size_t)(r0 + 8) * DIM + c0] = __halves2half2(l0, l1);
    }
}

// ---------------- launch ----------------------------------------------------
extern "C" void kernel_launch(void* const* d_in, const int* in_sizes, int n_in,
                              void* d_out, int out_size)
{
    const float* X    = (const float*)d_in[0];
    const float* mask = (const float*)d_in[1];
    const float* Wq   = (const float*)d_in[2];
    const float* bq   = (const float*)d_in[3];
    const float* Wk   = (const float*)d_in[4];
    const float* bk   = (const float*)d_in[5];
    const float* Wv   = (const float*)d_in[6];
    const float* bv   = (const float*)d_in[7];
    const float* Wo   = (const float*)d_in[8];
    const float* bo   = (const float*)d_in[9];
    float* out = (float*)d_out;

    __half *Xh, *Xl, *Wqh, *Wkh, *Wvh, *Woh;
    __half *Qh, *Ql, *Kh, *Kl, *Vh, *Vl, *Ch, *Cl;
    cudaGetSymbolAddress((void**)&Xh, g_Xh);   cudaGetSymbolAddress((void**)&Xl, g_Xl);
    cudaGetSymbolAddress((void**)&Wqh, g_Wqh);
    cudaGetSymbolAddress((void**)&Wkh, g_Wkh);
    cudaGetSymbolAddress((void**)&Wvh, g_Wvh);
    cudaGetSymbolAddress((void**)&Woh, g_Woh);
    cudaGetSymbolAddress((void**)&Qh, g_Qh);   cudaGetSymbolAddress((void**)&Ql, g_Ql);
    cudaGetSymbolAddress((void**)&Kh, g_Kh);   cudaGetSymbolAddress((void**)&Kl, g_Kl);
    cudaGetSymbolAddress((void**)&Vh, g_Vh);   cudaGetSymbolAddress((void**)&Vl, g_Vl);
    cudaGetSymbolAddress((void**)&Ch, g_Ch);   cudaGetSymbolAddress((void**)&Cl, g_Cl);

    const int nX4 = MROWS * DIM / 4;
    const int nW4 = DIM * DIM / 4;
    split_kernel<<<nX4 / 256, 256>>>((const float4*)X, (__half2*)Xh, (__half2*)Xl, nX4);
    dim3 wgrid(nW4 / 256, 4);
    splitw_kernel<<<wgrid, 256>>>((const float4*)Wq, (const float4*)Wk,
                                  (const float4*)Wv, (const float4*)Wo,
                                  (__half2*)Wqh, (__half2*)Wkh,
                                  (__half2*)Wvh, (__half2*)Woh, nW4);

    dim3 qkvgrid(DIM / 128, MROWS / 64, 3);   // (8, 64, 3)
    gemmqkv_kernel<<<qkvgrid, 256, GEMM_SMEM>>>(
        Xh, Xl, Wqh, Wkh, Wvh, bq, bk, bv,
        Qh, Ql, Kh, Kl, Vh, Vl);

    dim3 fgrid(SEQ / 128, NH, BATCH);         // (16, 16, 2)
    flash16_kernel<<<fgrid, 256>>>(Qh, Kh, Vh, mask, Ch, Cl);

    dim3 ogrid(DIM / 128, MROWS / 64);        // (8, 64)
    gemmo_kernel<<<ogrid, 256, GEMM_SMEM>>>(Ch, Cl, Woh, bo, out);
}

// round 17
// speedup vs baseline: 1.4975x; 1.4975x over previous
#include <cuda_runtime.h>
#include <cuda_fp16.h>
#include <math.h>
#include <stdint.h>

#define BATCH 2
#define SEQ   2048
#define DIM   1024
#define NH    16
#define DHD   64
#define MROWS (BATCH*SEQ)   // 4096

// ---------------- scratch (device globals: allocation-free) ----------------
__device__ __half g_Xh[(size_t)MROWS * DIM], g_Xl[(size_t)MROWS * DIM];
__device__ __half g_Wqh[(size_t)DIM * DIM];
__device__ __half g_Wkh[(size_t)DIM * DIM];
__device__ __half g_Wvh[(size_t)DIM * DIM];
__device__ __half g_Woh[(size_t)DIM * DIM];
__device__ __half g_Qh[(size_t)MROWS * DIM], g_Ql[(size_t)MROWS * DIM];
__device__ __half g_Kh[(size_t)MROWS * DIM];
__device__ __half g_Vh[(size_t)MROWS * DIM];
__device__ __half g_Ch[(size_t)MROWS * DIM], g_Cl[(size_t)MROWS * DIM];

// ---------------- helpers ---------------------------------------------------
__device__ __forceinline__ uint32_t smem_u32(const void* p) {
    return (uint32_t)__cvta_generic_to_shared(p);
}
__device__ __forceinline__ void cp16(uint32_t dst, const void* src) {
    asm volatile("cp.async.cg.shared.global [%0], [%1], 16;"
                 :: "r"(dst), "l"(src));
}
__device__ __forceinline__ void cp16p(void* dst, const void* src) {
    asm volatile("cp.async.cg.shared.global [%0], [%1], 16;"
                 :: "r"(smem_u32(dst)), "l"(src));
}
#define CP_COMMIT() asm volatile("cp.async.commit_group;")
#define CP_WAIT(n)  asm volatile("cp.async.wait_group %0;" :: "n"(n))

__device__ __forceinline__ void ldm_x4(uint32_t* r, uint32_t addr) {
    asm volatile("ldmatrix.sync.aligned.m8n8.x4.shared.b16 {%0,%1,%2,%3}, [%4];"
                 : "=r"(r[0]), "=r"(r[1]), "=r"(r[2]), "=r"(r[3]) : "r"(addr));
}
__device__ __forceinline__ void ldm_x4t(uint32_t* r, uint32_t addr) {
    asm volatile("ldmatrix.sync.aligned.m8n8.x4.trans.shared.b16 {%0,%1,%2,%3}, [%4];"
                 : "=r"(r[0]), "=r"(r[1]), "=r"(r[2]), "=r"(r[3]) : "r"(addr));
}
__device__ __forceinline__ void mma16(float* d, const uint32_t* a, const uint32_t* b) {
    asm volatile("mma.sync.aligned.m16n8k16.row.col.f32.f16.f16.f32 "
                 "{%0,%1,%2,%3}, {%4,%5,%6,%7}, {%8,%9}, {%0,%1,%2,%3};"
                 : "+f"(d[0]), "+f"(d[1]), "+f"(d[2]), "+f"(d[3])
                 : "r"(a[0]), "r"(a[1]), "r"(a[2]), "r"(a[3]),
                   "r"(b[0]), "r"(b[1]));
}
__device__ __forceinline__ float ex2f(float x) {
    float r;
    asm("ex2.approx.ftz.f32 %0, %1;" : "=f"(r) : "f"(x));
    return r;
}
__device__ __forceinline__ void split2(float x, __half& h, __half& l) {
    h = __float2half_rn(x);
    l = __float2half_rn(x - __half2float(h));
}

// ---------------- split kernels ---------------------------------------------
__global__ __launch_bounds__(256) void split_kernel(
    const float4* __restrict__ src, __half2* __restrict__ hi,
    __half2* __restrict__ lo, int n4)
{
    int i = blockIdx.x * 256 + threadIdx.x;
    if (i >= n4) return;
    float4 v = src[i];
    __half h0, l0, h1, l1;
    split2(v.x, h0, l0); split2(v.y, h1, l1);
    hi[2 * i]     = __halves2half2(h0, h1);
    lo[2 * i]     = __halves2half2(l0, l1);
    split2(v.z, h0, l0); split2(v.w, h1, l1);
    hi[2 * i + 1] = __halves2half2(h0, h1);
    lo[2 * i + 1] = __halves2half2(l0, l1);
}

// hi-only split for 4 weight matrices fused in one launch (blockIdx.y picks)
__global__ __launch_bounds__(256) void splitw_kernel(
    const float4* __restrict__ s0, const float4* __restrict__ s1,
    const float4* __restrict__ s2, const float4* __restrict__ s3,
    __half2* __restrict__ d0, __half2* __restrict__ d1,
    __half2* __restrict__ d2, __half2* __restrict__ d3, int n4)
{
    int w = blockIdx.y;
    const float4* s = (w == 0) ? s0 : (w == 1) ? s1 : (w == 2) ? s2 : s3;
    __half2* d      = (w == 0) ? d0 : (w == 1) ? d1 : (w == 2) ? d2 : d3;
    int i = blockIdx.x * 256 + threadIdx.x;
    if (i >= n4) return;
    float4 v = s[i];
    d[2 * i]     = __halves2half2(__float2half_rn(v.x), __float2half_rn(v.y));
    d[2 * i + 1] = __halves2half2(__float2half_rn(v.z), __float2half_rn(v.w));
}

// ============================================================================
// GEMM core: CTA 64x128, BK=32, warp 32x32, 2-term (Ah+Al)·Bh.
// Lo-output store is optional (o.Cl == nullptr skips it).
// ============================================================================
#define APITCH 40
#define BPITCH 136
#define A_BYTES (64 * APITCH * 2)
#define B_BYTES (32 * BPITCH * 2)
#define OFF_AH 0
#define OFF_AL A_BYTES
#define OFF_BH (2 * A_BYTES)
#define BUF_BYTES (2 * A_BYTES + B_BYTES)   // 18944
#define GEMM_SMEM (2 * BUF_BYTES)           // 37888

struct GemmOut {
    float*  Cf;
    __half* Ch;
    __half* Cl;
};

template<bool SPLIT_OUT>
__device__ __forceinline__ void gemm_body(
    const __half* __restrict__ Ah_g, const __half* __restrict__ Al_g,
    const __half* __restrict__ Bh_g,
    const float* __restrict__ bias, float out_scale, GemmOut o,
    int rowBase, int colBase, uint32_t sb)
{
    const int tid  = threadIdx.x;
    const int wid  = tid >> 5, lane = tid & 31;
    const int wrow = wid >> 2;
    const int wcol = wid & 3;
    const int rr = lane & 7, g = lane >> 3;

    float acc[2][4][4];
#pragma unroll
    for (int mt = 0; mt < 2; mt++)
#pragma unroll
        for (int nt = 0; nt < 4; nt++)
#pragma unroll
            for (int e = 0; e < 4; e++) acc[mt][nt][e] = 0.f;

    auto loadTile = [&](int buf, int k0) {
        uint32_t b = sb + buf * BUF_BYTES;
        {
            int r = tid >> 2, c16 = (tid & 3) << 4;
            size_t go = (size_t)(rowBase + r) * DIM + k0 + (c16 >> 1);
            uint32_t so = (uint32_t)(r * (APITCH * 2) + c16);
            cp16(b + OFF_AH + so, Ah_g + go);
            cp16(b + OFF_AL + so, Al_g + go);
        }
#pragma unroll
        for (int i = 0; i < 2; i++) {
            int idx = tid + i * 256;
            int r = idx >> 4, c16 = (idx & 15) << 4;
            size_t go = (size_t)(k0 + r) * DIM + colBase + (c16 >> 1);
            uint32_t so = (uint32_t)(r * (BPITCH * 2) + c16);
            cp16(b + OFF_BH + so, Bh_g + go);
        }
    };

    loadTile(0, 0); CP_COMMIT();

    const int T = DIM / 32;
#pragma unroll 1
    for (int t = 0; t < T; t++) {
        if (t + 1 < T) { loadTile((t + 1) & 1, (t + 1) * 32); CP_COMMIT(); CP_WAIT(1); }
        else           { CP_WAIT(0); }
        __syncthreads();

        const uint32_t bb = sb + (t & 1) * BUF_BYTES;

#pragma unroll
        for (int ks = 0; ks < 2; ks++) {
            const int kl = ks * 16;
            uint32_t ahf[2][4], alf[2][4];
#pragma unroll
            for (int mt = 0; mt < 2; mt++) {
                int row = wrow * 32 + mt * 16 + rr + ((g & 1) << 3);
                int col = kl + ((g >> 1) << 3);
                uint32_t off = (uint32_t)(row * (APITCH * 2) + col * 2);
                ldm_x4(ahf[mt], bb + OFF_AH + off);
                ldm_x4(alf[mt], bb + OFF_AL + off);
            }
#pragma unroll
            for (int ntp = 0; ntp < 2; ntp++) {
                int brow = kl + rr + (((lane >> 3) & 1) << 3);
                int bcol = wcol * 32 + ntp * 16 + ((lane >> 4) << 3);
                uint32_t off = (uint32_t)(brow * (BPITCH * 2) + bcol * 2);
                uint32_t bh[4];
                ldm_x4t(bh, bb + OFF_BH + off);
#pragma unroll
                for (int mt = 0; mt < 2; mt++) {
                    mma16(acc[mt][2 * ntp],     ahf[mt], bh);
                    mma16(acc[mt][2 * ntp],     alf[mt], bh);
                    mma16(acc[mt][2 * ntp + 1], ahf[mt], bh + 2);
                    mma16(acc[mt][2 * ntp + 1], alf[mt], bh + 2);
                }
            }
        }
        __syncthreads();
    }

#pragma unroll
    for (int mt = 0; mt < 2; mt++) {
        int r0 = rowBase + wrow * 32 + mt * 16 + (lane >> 2);
#pragma unroll
        for (int nt = 0; nt < 4; nt++) {
            int c0 = colBase + wcol * 32 + nt * 8 + ((lane & 3) << 1);
            float b0 = bias[c0], b1 = bias[c0 + 1];
            float v00 = (acc[mt][nt][0] + b0) * out_scale;
            float v01 = (acc[mt][nt][1] + b1) * out_scale;
            float v10 = (acc[mt][nt][2] + b0) * out_scale;
            float v11 = (acc[mt][nt][3] + b1) * out_scale;
            if (SPLIT_OUT) {
                __half h0, l0, h1, l1;
                split2(v00, h0, l0); split2(v01, h1, l1);
                *(__half2*)&o.Ch[(size_t)r0 * DIM + c0] = __halves2half2(h0, h1);
                if (o.Cl)
                    *(__half2*)&o.Cl[(size_t)r0 * DIM + c0] = __halves2half2(l0, l1);
                split2(v10, h0, l0); split2(v11, h1, l1);
                *(__half2*)&o.Ch[(size_t)(r0 + 8) * DIM + c0] = __halves2half2(h0, h1);
                if (o.Cl)
                    *(__half2*)&o.Cl[(size_t)(r0 + 8) * DIM + c0] = __halves2half2(l0, l1);
            } else {
                o.Cf[(size_t)r0 * DIM + c0]           = v00;
                o.Cf[(size_t)r0 * DIM + c0 + 1]       = v01;
                o.Cf[(size_t)(r0 + 8) * DIM + c0]     = v10;
                o.Cf[(size_t)(r0 + 8) * DIM + c0 + 1] = v11;
            }
        }
    }
}

__global__ __launch_bounds__(256) void gemmqkv_kernel(
    const __half* __restrict__ Xh, const __half* __restrict__ Xl,
    const __half* __restrict__ Wqh, const __half* __restrict__ Wkh,
    const __half* __restrict__ Wvh,
    const float* __restrict__ bq, const float* __restrict__ bk,
    const float* __restrict__ bv,
    __half* __restrict__ Qh, __half* __restrict__ Ql,
    __half* __restrict__ Kh, __half* __restrict__ Vh)
{
    extern __shared__ __align__(16) char dsm[];
    const int z = blockIdx.z;
    const __half* Bh = (z == 0) ? Wqh : (z == 1) ? Wkh : Wvh;
    const float*  bs = (z == 0) ? bq  : (z == 1) ? bk  : bv;
    GemmOut o;
    o.Cf = nullptr;
    o.Ch = (z == 0) ? Qh : (z == 1) ? Kh : Vh;
    o.Cl = (z == 0) ? Ql : nullptr;            // lo only needed for Q
    // Q scale folds 1/sqrt(64) AND log2(e) so softmax can use raw ex2.
    float sc = (z == 0) ? (0.125f * 1.44269504f) : 1.0f;
    gemm_body<true>(Xh, Xl, Bh, bs, sc, o,
                    blockIdx.y * 64, blockIdx.x * 128, smem_u32(dsm));
}

__global__ __launch_bounds__(256) void gemmo_kernel(
    const __half* __restrict__ Ah, const __half* __restrict__ Al,
    const __half* __restrict__ Bh,
    const float* __restrict__ bias, float* __restrict__ out)
{
    extern __shared__ __align__(16) char dsm[];
    GemmOut o; o.Cf = out; o.Ch = nullptr; o.Cl = nullptr;
    gemm_body<false>(Ah, Al, Bh, bias, 1.0f, o,
                     blockIdx.y * 64, blockIdx.x * 128, smem_u32(dsm));
}

// ============================================================================
// Flash attention — 2-term scores (Qh+Ql)·Kh, 1-term PV Ph·Vh.
// Softmax in log2 domain (scale pre-folded): raw ex2.approx, no mul.
// Warp-uniform skip of ctx rescale when running max is unchanged.
// K/V hi-only smem, 2 CTAs/SM, 256 threads, 128 q-rows, double-buffered.
// ============================================================================
#define FPAD 72
#define KVOFF_V 2304   // 32*FPAD halfs
#define MLOG2E 1442695.0f   // 1e6 * log2(e)

__global__ __launch_bounds__(256, 2) void flash16_kernel(
    const __half* __restrict__ Qh_g, const __half* __restrict__ Ql_g,
    const __half* __restrict__ Kh_g, const __half* __restrict__ Vh_g,
    const float* __restrict__ mask,
    __half* __restrict__ Ch_g, __half* __restrict__ Cl_g)
{
    __shared__ __align__(16) __half fsm[2][128 * FPAD];   // Q staging, then K/V x2
    __shared__ __align__(16) float maskS[2][32];

    const int b = blockIdx.z, h = blockIdx.y;
    const int q0 = blockIdx.x * 128;
    const int tid = threadIdx.x, wid = tid >> 5, lane = tid & 31;
    const int rr = lane & 7, g = lane >> 3;
    const size_t base = ((size_t)b * SEQ) * DIM + (size_t)h * DHD;

    // ---- stage Q (hi+lo), preload fragments ----
#pragma unroll
    for (int i = 0; i < 4; i++) {
        int idx = tid + i * 256;
        int r = idx >> 3, c8 = (idx & 7) << 3;
        size_t go = base + (size_t)(q0 + r) * DIM + c8;
        cp16p(&fsm[0][r * FPAD + c8], Qh_g + go);
        cp16p(&fsm[1][r * FPAD + c8], Ql_g + go);
    }
    CP_COMMIT(); CP_WAIT(0);
    __syncthreads();

    const int m0 = wid * 16;
    const int qrow = m0 + rr + ((g & 1) << 3);
    const int qcoff = (g >> 1) << 3;
    uint32_t qfh[4][4], qfl[4][4];
#pragma unroll
    for (int ks = 0; ks < 4; ks++) {
        ldm_x4(qfh[ks], smem_u32(&fsm[0][qrow * FPAD + ks * 16 + qcoff]));
        ldm_x4(qfl[ks], smem_u32(&fsm[1][qrow * FPAD + ks * 16 + qcoff]));
    }
    __syncthreads();   // Q smem reusable as K/V double buffer

    auto loadKV = [&](int buf, int kt) {
        __half* s = fsm[buf];
        int r = tid >> 3, c8 = (tid & 7) << 3;
        size_t go = base + (size_t)(kt + r) * DIM + c8;
        cp16p(&s[          r * FPAD + c8], Kh_g + go);
        cp16p(&s[KVOFF_V + r * FPAD + c8], Vh_g + go);
        if (tid < 8) cp16p(&maskS[buf][tid * 4], mask + (size_t)b * SEQ + kt + tid * 4);
    };

    float m0r = -1e30f, m1r = -1e30f, l0r = 0.f, l1r = 0.f;
    float ctx[8][4];
#pragma unroll
    for (int nt = 0; nt < 8; nt++)
#pragma unroll
        for (int e = 0; e < 4; e++) ctx[nt][e] = 0.f;

    loadKV(0, 0); CP_COMMIT();

#pragma unroll 1
    for (int t = 0; t < SEQ / 32; t++) {
        if (t < SEQ / 32 - 1) { loadKV((t + 1) & 1, (t + 1) * 32); CP_COMMIT(); }
        if (t < SEQ / 32 - 1) { CP_WAIT(1); } else { CP_WAIT(0); }
        __syncthreads();

        const __half* Ks = fsm[t & 1];
        const float*  mS = maskS[t & 1];

        // ---- scores S[16x32] (log2 units): (Qh + Ql) · Kh ----
        float s[4][4];
#pragma unroll
        for (int nt = 0; nt < 4; nt++)
#pragma unroll
            for (int e = 0; e < 4; e++) s[nt][e] = 0.f;

#pragma unroll
        for (int ks = 0; ks < 4; ks++) {
#pragma unroll
            for (int ntp = 0; ntp < 2; ntp++) {
                int krow = ntp * 16 + ((lane >> 4) << 3) + rr;
                int kcol = ks * 16 + (((lane >> 3) & 1) << 3);
                uint32_t kh[4];
                ldm_x4(kh, smem_u32(&Ks[krow * FPAD + kcol]));
                mma16(s[2 * ntp],     qfh[ks], kh);
                mma16(s[2 * ntp],     qfl[ks], kh);
                mma16(s[2 * ntp + 1], qfh[ks], kh + 2);
                mma16(s[2 * ntp + 1], qfl[ks], kh + 2);
            }
        }

        // ---- mask (log2 units) ----
#pragma unroll
        for (int nt = 0; nt < 4; nt++) {
            int c = nt * 8 + ((lane & 3) << 1);
            float mv0 = fmaf(mS[c],     MLOG2E, -MLOG2E);
            float mv1 = fmaf(mS[c + 1], MLOG2E, -MLOG2E);
            s[nt][0] += mv0; s[nt][1] += mv1;
            s[nt][2] += mv0; s[nt][3] += mv1;
        }

        // ---- online softmax (base-2) ----
        float rmax0 = -1e30f, rmax1 = -1e30f;
#pragma unroll
        for (int nt = 0; nt < 4; nt++) {
            rmax0 = fmaxf(rmax0, fmaxf(s[nt][0], s[nt][1]));
            rmax1 = fmaxf(rmax1, fmaxf(s[nt][2], s[nt][3]));
        }
        rmax0 = fmaxf(rmax0, __shfl_xor_sync(0xffffffffu, rmax0, 1));
        rmax0 = fmaxf(rmax0, __shfl_xor_sync(0xffffffffu, rmax0, 2));
        rmax1 = fmaxf(rmax1, __shfl_xor_sync(0xffffffffu, rmax1, 1));
        rmax1 = fmaxf(rmax1, __shfl_xor_sync(0xffffffffu, rmax1, 2));
        float newm0 = fmaxf(m0r, rmax0), newm1 = fmaxf(m1r, rmax1);
        bool upd = (newm0 > m0r) || (newm1 > m1r);

        float p[4][4];
        float rsum0 = 0.f, rsum1 = 0.f;
#pragma unroll
        for (int nt = 0; nt < 4; nt++) {
            p[nt][0] = ex2f(s[nt][0] - newm0);
            p[nt][1] = ex2f(s[nt][1] - newm0);
            p[nt][2] = ex2f(s[nt][2] - newm1);
            p[nt][3] = ex2f(s[nt][3] - newm1);
            rsum0 += p[nt][0] + p[nt][1];
            rsum1 += p[nt][2] + p[nt][3];
        }
        rsum0 += __shfl_xor_sync(0xffffffffu, rsum0, 1);
        rsum0 += __shfl_xor_sync(0xffffffffu, rsum0, 2);
        rsum1 += __shfl_xor_sync(0xffffffffu, rsum1, 1);
        rsum1 += __shfl_xor_sync(0xffffffffu, rsum1, 2);

        if (__any_sync(0xffffffffu, upd)) {
            float fac0 = ex2f(m0r - newm0), fac1 = ex2f(m1r - newm1);
            l0r = l0r * fac0 + rsum0;
            l1r = l1r * fac1 + rsum1;
#pragma unroll
            for (int nt = 0; nt < 8; nt++) {
                ctx[nt][0] *= fac0; ctx[nt][1] *= fac0;
                ctx[nt][2] *= fac1; ctx[nt][3] *= fac1;
            }
            m0r = newm0; m1r = newm1;
        } else {
            l0r += rsum0;
            l1r += rsum1;
        }

        // ---- pack P hi A-fragments (single term) ----
        uint32_t pah[2][4];
#pragma unroll
        for (int kb = 0; kb < 2; kb++) {
            int t0 = kb * 2, t1 = kb * 2 + 1;
            __half h0, h1;
            h0 = __float2half_rn(p[t0][0]); h1 = __float2half_rn(p[t0][1]);
            pah[kb][0] = (uint32_t)__half_as_ushort(h0) | ((uint32_t)__half_as_ushort(h1) << 16);
            h0 = __float2half_rn(p[t0][2]); h1 = __float2half_rn(p[t0][3]);
            pah[kb][1] = (uint32_t)__half_as_ushort(h0) | ((uint32_t)__half_as_ushort(h1) << 16);
            h0 = __float2half_rn(p[t1][0]); h1 = __float2half_rn(p[t1][1]);
            pah[kb][2] = (uint32_t)__half_as_ushort(h0) | ((uint32_t)__half_as_ushort(h1) << 16);
            h0 = __float2half_rn(p[t1][2]); h1 = __float2half_rn(p[t1][3]);
            pah[kb][3] = (uint32_t)__half_as_ushort(h0) | ((uint32_t)__half_as_ushort(h1) << 16);
        }

        // ---- ctx += Ph · Vh ----
#pragma unroll
        for (int kb = 0; kb < 2; kb++) {
            int vrow = kb * 16 + rr + (((lane >> 3) & 1) << 3);
#pragma unroll
            for (int ntp = 0; ntp < 4; ntp++) {
                int vcol = ntp * 16 + ((lane >> 4) << 3);
                uint32_t vh[4];
                ldm_x4t(vh, smem_u32(&Ks[KVOFF_V + vrow * FPAD + vcol]));
                mma16(ctx[2 * ntp],     pah[kb], vh);
                mma16(ctx[2 * ntp + 1], pah[kb], vh + 2);
            }
        }
        __syncthreads();
    }

    float inv0 = 1.f / l0r, inv1 = 1.f / l1r;
    int r0 = q0 + m0 + (lane >> 2);
#pragma unroll
    for (int nt = 0; nt < 8; nt++) {
        int c0 = nt * 8 + ((lane & 3) << 1);
        __half h0, l0, h1, l1;
        split2(ctx[nt][0] * inv0, h0, l0); split2(ctx[nt][1] * inv0, h1, l1);
        *(__half2*)&Ch_g[base + (size_t)r0 * DIM + c0] = __halves2half2(h0, h1);
        *(__half2*)&Cl_g[base + (size_t)r0 * DIM + c0] = __halves2half2(l0, l1);
        split2(ctx[nt][2] * inv1, h0, l0); split2(ctx[nt][3] * inv1, h1, l1);
        *(__half2*)&Ch_g[base + (size_t)(r0 + 8) * DIM + c0] = __halves2half2(h0, h1);
        *(__half2*)&Cl_g[base + (size_t)(r0 + 8) * DIM + c0] = __halves2half2(l0, l1);
    }
}

// ---------------- launch ----------------------------------------------------
extern "C" void kernel_launch(void* const* d_in, const int* in_sizes, int n_in,
                              void* d_out, int out_size)
{
    const float* X    = (const float*)d_in[0];
    const float* mask = (const float*)d_in[1];
    const float* Wq   = (const float*)d_in[2];
    const float* bq   = (const float*)d_in[3];
    const float* Wk   = (const float*)d_in[4];
    const float* bk   = (const float*)d_in[5];
    const float* Wv   = (const float*)d_in[6];
    const float* bv   = (const float*)d_in[7];
    const float* Wo   = (const float*)d_in[8];
    const float* bo   = (const float*)d_in[9];
    float* out = (float*)d_out;

    __half *Xh, *Xl, *Wqh, *Wkh, *Wvh, *Woh;
    __half *Qh, *Ql, *Kh, *Vh, *Ch, *Cl;
    cudaGetSymbolAddress((void**)&Xh, g_Xh);   cudaGetSymbolAddress((void**)&Xl, g_Xl);
    cudaGetSymbolAddress((void**)&Wqh, g_Wqh);
    cudaGetSymbolAddress((void**)&Wkh, g_Wkh);
    cudaGetSymbolAddress((void**)&Wvh, g_Wvh);
    cudaGetSymbolAddress((void**)&Woh, g_Woh);
    cudaGetSymbolAddress((void**)&Qh, g_Qh);   cudaGetSymbolAddress((void**)&Ql, g_Ql);
    cudaGetSymbolAddress((void**)&Kh, g_Kh);
    cudaGetSymbolAddress((void**)&Vh, g_Vh);
    cudaGetSymbolAddress((void**)&Ch, g_Ch);   cudaGetSymbolAddress((void**)&Cl, g_Cl);

    const int nX4 = MROWS * DIM / 4;
    const int nW4 = DIM * DIM / 4;
    split_kernel<<<nX4 / 256, 256>>>((const float4*)X, (__half2*)Xh, (__half2*)Xl, nX4);
    dim3 wgrid(nW4 / 256, 4);
    splitw_kernel<<<wgrid, 256>>>((const float4*)Wq, (const float4*)Wk,
                                  (const float4*)Wv, (const float4*)Wo,
                                  (__half2*)Wqh, (__half2*)Wkh,
                                  (__half2*)Wvh, (__half2*)Woh, nW4);

    dim3 qkvgrid(DIM / 128, MROWS / 64, 3);   // (8, 64, 3)
    gemmqkv_kernel<<<qkvgrid, 256, GEMM_SMEM>>>(
        Xh, Xl, Wqh, Wkh, Wvh, bq, bk, bv,
        Qh, Ql, Kh, Vh);

    dim3 fgrid(SEQ / 128, NH, BATCH);         // (16, 16, 2)
    flash16_kernel<<<fgrid, 256>>>(Qh, Ql, Kh, Vh, mask, Ch, Cl);

    dim3 ogrid(DIM / 128, MROWS / 64);        // (8, 64)
    gemmo_kernel<<<ogrid, 256, GEMM_SMEM>>>(Ch, Cl, Woh, bo, out);
}